// round 1
// baseline (speedup 1.0000x reference)
#include <cuda_runtime.h>
#include <cuda_bf16.h>

// Problem constants (match reference: NUM_CLASSES=5532, F=256, Q=2*NUM_CLASSES)
#define NC   5532
#define FEAT 256
#define NV4  (FEAT / 4)   // 64 float4 per row

// Scratch (device globals — no allocation allowed)
__device__ float4 g_sums[NC * NV4];   // per-class feature sums, float4-packed
__device__ int    g_counts[NC];       // per-class row counts
__device__ int    g_rank[NC];         // exclusive rank among present classes

// ---------------------------------------------------------------------------
// 1) Zero the scratch accumulators
// ---------------------------------------------------------------------------
__global__ void zero_kernel() {
    const int total = NC * NV4;
    for (int i = blockIdx.x * blockDim.x + threadIdx.x; i < total;
         i += gridDim.x * blockDim.x) {
        g_sums[i] = make_float4(0.f, 0.f, 0.f, 0.f);
        if (i < NC) g_counts[i] = 0;
    }
}

// ---------------------------------------------------------------------------
// 2) Initialize output = [queue (Q*FEAT floats) | queue_label (Q floats)]
//    Both sections are float4-divisible (Q = 11064, Q*FEAT huge).
// ---------------------------------------------------------------------------
__global__ void init_out_kernel(const float4* __restrict__ queue_in,
                                const float4* __restrict__ label_in,
                                float4* __restrict__ out,
                                int nq4, int nl4) {
    const int total = nq4 + nl4;
    for (int i = blockIdx.x * blockDim.x + threadIdx.x; i < total;
         i += gridDim.x * blockDim.x) {
        out[i] = (i < nq4) ? queue_in[i] : label_in[i - nq4];
    }
}

// ---------------------------------------------------------------------------
// 3) Accumulate: one warp per feature row. Coalesced float4 loads of the
//    1 KB row, vector RED into the class accumulator (sm_90+ float4 atomics).
// ---------------------------------------------------------------------------
__global__ void accum_kernel(const float4* __restrict__ feat,
                             const int* __restrict__ labels, int N) {
    int warp = (blockIdx.x * blockDim.x + threadIdx.x) >> 5;
    int lane = threadIdx.x & 31;
    if (warp >= N) return;

    int c = labels[warp];
    if (c < 0 || c >= NC) return;   // reference drops negative / OOR labels

    if (lane == 0) atomicAdd(&g_counts[c], 1);

    const float4* row = feat + (size_t)warp * NV4;
    float4 v0 = row[lane];
    float4 v1 = row[lane + 32];

    float4* dst = &g_sums[c * NV4];
    // Vector atomic add (red.global.add.v4.f32) — native on sm_90+
    atomicAdd(&dst[lane], v0);
    atomicAdd(&dst[lane + 32], v1);
}

// ---------------------------------------------------------------------------
// 4) Rank scan: exclusive prefix over "present" flags (counts > 0), sorted
//    label order == index order. One block of 1024 threads, CHUNK=6 each.
// ---------------------------------------------------------------------------
__global__ void rank_scan_kernel() {
    __shared__ int s[1024];
    const int CHUNK = (NC + 1023) / 1024;   // 6
    int t = threadIdx.x;
    int base = t * CHUNK;

    int pres[6];
    int local = 0;
#pragma unroll
    for (int k = 0; k < CHUNK; k++) {
        int c = base + k;
        int p = (c < NC && g_counts[c] > 0) ? 1 : 0;
        pres[k] = p;
        local += p;
    }
    s[t] = local;
    __syncthreads();

    // Hillis–Steele inclusive scan over 1024 partials
#pragma unroll
    for (int off = 1; off < 1024; off <<= 1) {
        int v = (t >= off) ? s[t - off] : 0;
        __syncthreads();
        s[t] += v;
        __syncthreads();
    }

    int excl = s[t] - local;   // exclusive prefix for this thread's chunk
#pragma unroll
    for (int k = 0; k < CHUNK; k++) {
        int c = base + k;
        if (c < NC && pres[k]) {
            g_rank[c] = excl;
            excl += 1;
        }
    }
}

// ---------------------------------------------------------------------------
// 5) Scatter: one block (64 threads) per class. Scale sums by 1/count and
//    write the queue row at pos = (tail + rank) % Q; thread 0 writes label.
// ---------------------------------------------------------------------------
__global__ void scatter_kernel(float* __restrict__ out,
                               const int* __restrict__ tail_p, int Q) {
    int c = blockIdx.x;
    int cnt = g_counts[c];
    if (cnt == 0) return;

    int tail = tail_p[0];
    int r = g_rank[c];
    int pos = (tail + r) % Q;
    if (pos < 0) pos += Q;

    float inv = 1.0f / (float)cnt;
    int j = threadIdx.x;   // 0..63

    float4 v = g_sums[c * NV4 + j];
    v.x *= inv; v.y *= inv; v.z *= inv; v.w *= inv;

    float4* oq = (float4*)out;
    oq[(size_t)pos * NV4 + j] = v;

    if (j == 0) out[(size_t)Q * FEAT + pos] = (float)c;
}

// ---------------------------------------------------------------------------
// Launch
// Inputs (metadata order): features f32[N,256], pid_labels i32[N],
//   large_batch_queue f32[Q,256], queue_label f32[Q], tail i32[1]
// Output: [new_queue f32[Q,256] | new_label f32[Q]] flattened
// ---------------------------------------------------------------------------
extern "C" void kernel_launch(void* const* d_in, const int* in_sizes, int n_in,
                              void* d_out, int out_size) {
    const float4* feat    = (const float4*)d_in[0];
    const int*    labels  = (const int*)d_in[1];
    const float4* queue0  = (const float4*)d_in[2];
    const float4* qlabel0 = (const float4*)d_in[3];
    const int*    tail_p  = (const int*)d_in[4];

    int N = in_sizes[1];          // 131072
    int Q = in_sizes[3];          // 11064
    float* out = (float*)d_out;

    // 1) zero accumulators
    {
        int total = NC * NV4;
        int threads = 256;
        int blocks = (total + threads - 1) / threads;
        zero_kernel<<<blocks, threads>>>();
    }
    // 2) init output from input queue + labels
    {
        int nq4 = Q * NV4;        // Q*256/4
        int nl4 = Q / 4;
        int total = nq4 + nl4;
        int threads = 256;
        int blocks = (total + threads - 1) / threads;
        init_out_kernel<<<blocks, threads>>>(queue0, qlabel0, (float4*)out,
                                             nq4, nl4);
    }
    // 3) accumulate (1 warp per row)
    {
        int threads = 256;                 // 8 warps per block
        int rows_per_block = threads / 32;
        int blocks = (N + rows_per_block - 1) / rows_per_block;
        accum_kernel<<<blocks, threads>>>(feat, labels, N);
    }
    // 4) rank scan
    rank_scan_kernel<<<1, 1024>>>();
    // 5) scatter means + labels
    scatter_kernel<<<NC, NV4>>>(out, tail_p, Q);
}

// round 2
// speedup vs baseline: 1.0632x; 1.0632x over previous
#include <cuda_runtime.h>
#include <cuda_bf16.h>

// Problem constants (reference: NUM_CLASSES=5532, F=256, Q=2*NUM_CLASSES, N=131072)
#define NC    5532
#define FEAT  256
#define NV4   (FEAT / 4)     // 64 float4 per row
#define NMAX  131072

// Scratch (device globals — allocation is forbidden)
__device__ int g_cnt[NC];        // per-class row counts
__device__ int g_cur[NC];        // per-class bucket cursors
__device__ int g_off[NC];        // exclusive prefix of counts (bucket base)
__device__ int g_pos[NC];        // final queue row for each present class
__device__ int g_bucket[NMAX];   // row indices grouped by class

// ---------------------------------------------------------------------------
// 1) Init output = [queue | queue_label] and zero the histogram counters.
// ---------------------------------------------------------------------------
__global__ void init_out_kernel(const float4* __restrict__ queue_in,
                                const float4* __restrict__ label_in,
                                float4* __restrict__ out,
                                int nq4, int nl4) {
    int i = blockIdx.x * blockDim.x + threadIdx.x;
    if (i < NC) g_cnt[i] = 0;
    const int total = nq4 + nl4;
    if (i < total)
        out[i] = (i < nq4) ? queue_in[i] : label_in[i - nq4];
}

// ---------------------------------------------------------------------------
// 2) Histogram: per-class row counts (int atomics only — cheap at the LTS).
// ---------------------------------------------------------------------------
__global__ void histo_kernel(const int* __restrict__ labels, int N) {
    int i = blockIdx.x * blockDim.x + threadIdx.x;
    if (i >= N) return;
    int c = labels[i];
    if (c >= 0 && c < NC) atomicAdd(&g_cnt[c], 1);
}

// ---------------------------------------------------------------------------
// 3) Scan: one block, warp-shuffle two-level scan (2 barriers total).
//    Produces g_off (exclusive count prefix), g_pos ((tail+rank)%Q for
//    present classes), and zeroes g_cur.
// ---------------------------------------------------------------------------
__global__ void scan_kernel(const int* __restrict__ tail_p, int Q) {
    const int CHUNK = 6;                     // ceil(5532/1024)
    int t    = threadIdx.x;
    int lane = t & 31;
    int warp = t >> 5;
    int base = t * CHUNK;

    int cnts[CHUNK];
    int lc = 0, lp = 0;
#pragma unroll
    for (int k = 0; k < CHUNK; k++) {
        int c = base + k;
        int v = (c < NC) ? g_cnt[c] : 0;
        cnts[k] = v;
        lc += v;
        lp += (v > 0);
    }

    // warp inclusive scan of (lc, lp)
    int ic = lc, ip = lp;
#pragma unroll
    for (int off = 1; off < 32; off <<= 1) {
        int vc = __shfl_up_sync(0xffffffffu, ic, off);
        int vp = __shfl_up_sync(0xffffffffu, ip, off);
        if (lane >= off) { ic += vc; ip += vp; }
    }

    __shared__ int wc[32], wp[32];
    if (lane == 31) { wc[warp] = ic; wp[warp] = ip; }
    __syncthreads();
    if (warp == 0) {
        int vc = wc[lane], vp = wp[lane];
#pragma unroll
        for (int off = 1; off < 32; off <<= 1) {
            int tc = __shfl_up_sync(0xffffffffu, vc, off);
            int tp = __shfl_up_sync(0xffffffffu, vp, off);
            if (lane >= off) { vc += tc; vp += tp; }
        }
        wc[lane] = vc; wp[lane] = vp;
    }
    __syncthreads();

    int offc = ic - lc + (warp ? wc[warp - 1] : 0);   // exclusive count prefix
    int offp = ip - lp + (warp ? wp[warp - 1] : 0);   // exclusive rank prefix
    int tail = *tail_p;

#pragma unroll
    for (int k = 0; k < CHUNK; k++) {
        int c = base + k;
        if (c < NC) {
            g_off[c] = offc;
            g_cur[c] = 0;
            if (cnts[k] > 0) {
                int pos = (tail + offp) % Q;
                if (pos < 0) pos += Q;
                g_pos[c] = pos;
                offp++;
            }
            offc += cnts[k];
        }
    }
}

// ---------------------------------------------------------------------------
// 4) Bucket: group row indices by class.
// ---------------------------------------------------------------------------
__global__ void bucket_kernel(const int* __restrict__ labels, int N) {
    int i = blockIdx.x * blockDim.x + threadIdx.x;
    if (i >= N) return;
    int c = labels[i];
    if (c >= 0 && c < NC) {
        int s = atomicAdd(&g_cur[c], 1);
        g_bucket[g_off[c] + s] = i;
    }
}

// ---------------------------------------------------------------------------
// 5) Gather + mean + scatter: one 64-thread block per class. Register
//    accumulation (no float atomics), 4-row unroll for MLP, streaming loads
//    (features are read exactly once; 134 MB > L2). Writes the mean directly
//    to its final circular-queue slot and the class label.
// ---------------------------------------------------------------------------
__global__ void mean_kernel(const float4* __restrict__ feat,
                            float* __restrict__ out, int Q) {
    int c = blockIdx.x;
    int cnt = g_cnt[c];
    if (cnt == 0) return;

    int base = g_off[c];
    int pos  = g_pos[c];
    int t    = threadIdx.x;           // 0..63 (one float4 column per thread)

    __shared__ int sidx[64];
    float4 acc = make_float4(0.f, 0.f, 0.f, 0.f);

    for (int start = 0; start < cnt; start += 64) {
        int nb = min(64, cnt - start);
        if (t < nb) sidx[t] = g_bucket[base + start + t];
        __syncthreads();

        int r = 0;
        for (; r + 4 <= nb; r += 4) {
            float4 v0 = __ldcs(feat + (size_t)sidx[r + 0] * NV4 + t);
            float4 v1 = __ldcs(feat + (size_t)sidx[r + 1] * NV4 + t);
            float4 v2 = __ldcs(feat + (size_t)sidx[r + 2] * NV4 + t);
            float4 v3 = __ldcs(feat + (size_t)sidx[r + 3] * NV4 + t);
            acc.x += v0.x + v1.x + v2.x + v3.x;
            acc.y += v0.y + v1.y + v2.y + v3.y;
            acc.z += v0.z + v1.z + v2.z + v3.z;
            acc.w += v0.w + v1.w + v2.w + v3.w;
        }
        for (; r < nb; r++) {
            float4 v = __ldcs(feat + (size_t)sidx[r] * NV4 + t);
            acc.x += v.x; acc.y += v.y; acc.z += v.z; acc.w += v.w;
        }
        __syncthreads();
    }

    float inv = 1.0f / (float)cnt;
    float4 o = make_float4(acc.x * inv, acc.y * inv, acc.z * inv, acc.w * inv);
    ((float4*)out)[(size_t)pos * NV4 + t] = o;
    if (t == 0) out[(size_t)Q * FEAT + pos] = (float)c;
}

// ---------------------------------------------------------------------------
// Launch
// Inputs: features f32[N,256], pid_labels i32[N], large_batch_queue f32[Q,256],
//         queue_label f32[Q], tail i32[1]
// Output: [new_queue f32[Q,256] | new_label f32[Q]]
// ---------------------------------------------------------------------------
extern "C" void kernel_launch(void* const* d_in, const int* in_sizes, int n_in,
                              void* d_out, int out_size) {
    const float4* feat    = (const float4*)d_in[0];
    const int*    labels  = (const int*)d_in[1];
    const float4* queue0  = (const float4*)d_in[2];
    const float4* qlabel0 = (const float4*)d_in[3];
    const int*    tail_p  = (const int*)d_in[4];

    int N = in_sizes[1];              // 131072
    int Q = in_sizes[3];              // 11064
    float* out = (float*)d_out;

    // 1) init output + zero counts
    {
        int nq4 = Q * NV4;
        int nl4 = Q / 4;
        int total = nq4 + nl4;        // > NC, so counts fully zeroed too
        int threads = 256;
        int blocks = (total + threads - 1) / threads;
        init_out_kernel<<<blocks, threads>>>(queue0, qlabel0, (float4*)out,
                                             nq4, nl4);
    }
    // 2) histogram
    {
        int threads = 256;
        int blocks = (N + threads - 1) / threads;
        histo_kernel<<<blocks, threads>>>(labels, N);
    }
    // 3) scan (offsets, positions, cursor reset)
    scan_kernel<<<1, 1024>>>(tail_p, Q);
    // 4) bucket row indices by class
    {
        int threads = 256;
        int blocks = (N + threads - 1) / threads;
        bucket_kernel<<<blocks, threads>>>(labels, N);
    }
    // 5) gather rows, compute means, scatter into queue
    mean_kernel<<<NC, 64>>>(feat, out, Q);
}

// round 3
// speedup vs baseline: 1.2461x; 1.1721x over previous
#include <cuda_runtime.h>
#include <cuda_bf16.h>

// Problem constants (reference: NUM_CLASSES=5532, F=256, Q=2*NUM_CLASSES, N=131072)
#define NC    5532
#define FEAT  256
#define NV4   (FEAT / 4)     // 64 float4 per row
#define CAP   128            // per-class bucket capacity (counts ~ Poisson(23.7))

// Scratch (device globals — zero-initialized at module load; g_cnt is
// self-resetting: mean_kernel zeroes it after use, so every call sees zeros)
__device__ int g_cnt[NC];            // per-class counts (atomic tickets)
__device__ int g_pos[NC];            // final queue row for present classes
__device__ int g_bucket[NC * CAP];   // per-class row indices
__device__ int g_wstart;             // circular write-window start
__device__ int g_wlen;               // circular write-window length (#present)

// ---------------------------------------------------------------------------
// 1) Count + bucket in ONE pass: the atomic ticket IS the bucket slot.
// ---------------------------------------------------------------------------
__global__ void bucket_count_kernel(const int* __restrict__ labels, int N) {
    int i = blockIdx.x * blockDim.x + threadIdx.x;
    if (i >= N) return;
    int c = labels[i];
    if (c < 0 || c >= NC) return;
    int s = atomicAdd(&g_cnt[c], 1);
    if (s < CAP) g_bucket[c * CAP + s] = i;
}

// ---------------------------------------------------------------------------
// 2) Presence scan: rank among present classes -> queue position, plus the
//    circular window [wstart, wstart+wlen) that mean_kernel will overwrite.
//    One block, warp-shuffle two-level scan.
// ---------------------------------------------------------------------------
__global__ void scan_kernel(const int* __restrict__ tail_p, int Q) {
    const int CHUNK = 6;                     // ceil(5532/1024)
    int t    = threadIdx.x;
    int lane = t & 31;
    int warp = t >> 5;
    int base = t * CHUNK;

    int pres[CHUNK];
    int lp = 0;
#pragma unroll
    for (int k = 0; k < CHUNK; k++) {
        int c = base + k;
        int p = (c < NC && g_cnt[c] > 0) ? 1 : 0;
        pres[k] = p;
        lp += p;
    }

    // warp inclusive scan
    int ip = lp;
#pragma unroll
    for (int off = 1; off < 32; off <<= 1) {
        int v = __shfl_up_sync(0xffffffffu, ip, off);
        if (lane >= off) ip += v;
    }

    __shared__ int wp[32];
    if (lane == 31) wp[warp] = ip;
    __syncthreads();
    if (warp == 0) {
        int v = wp[lane];
#pragma unroll
        for (int off = 1; off < 32; off <<= 1) {
            int u = __shfl_up_sync(0xffffffffu, v, off);
            if (lane >= off) v += u;
        }
        wp[lane] = v;
    }
    __syncthreads();

    int tail = *tail_p;
    int ws = tail % Q; if (ws < 0) ws += Q;

    int offp = ip - lp + (warp ? wp[warp - 1] : 0);   // exclusive rank
#pragma unroll
    for (int k = 0; k < CHUNK; k++) {
        int c = base + k;
        if (c < NC && pres[k]) {
            int pos = ws + offp;
            if (pos >= Q) pos -= Q;
            g_pos[c] = pos;
            offp++;
        }
    }

    if (t == 0) {
        g_wstart = ws;
        g_wlen   = wp[31];    // total present classes
    }
}

// ---------------------------------------------------------------------------
// 3) Init output = [queue | label], SKIPPING rows inside the write window
//    (those are produced solely by mean_kernel). Saves ~half the output
//    traffic and the corresponding queue reads.
// ---------------------------------------------------------------------------
__global__ void init_out_kernel(const float4* __restrict__ queue_in,
                                const float* __restrict__ label_in,
                                float* __restrict__ out, int Q) {
    int nq4 = Q * NV4;
    int i = blockIdx.x * blockDim.x + threadIdx.x;
    int ws = g_wstart, wl = g_wlen;

    if (i < nq4) {
        int row = i >> 6;                 // NV4 = 64
        int d = row - ws; if (d < 0) d += Q;
        if (d >= wl) ((float4*)out)[i] = queue_in[i];
    } else {
        int j = i - nq4;
        if (j < Q) {
            int d = j - ws; if (d < 0) d += Q;
            if (d >= wl) out[(size_t)Q * FEAT + j] = label_in[j];
        }
    }
}

// ---------------------------------------------------------------------------
// 4) Gather + mean + scatter: one 64-thread block per class. Register
//    accumulation, 8-row unroll for MLP, streaming loads (features read
//    exactly once). Self-resets g_cnt. Slow generic fallback if cnt > CAP
//    (never taken for this distribution, kept for correctness).
// ---------------------------------------------------------------------------
__global__ void mean_kernel(const float4* __restrict__ feat,
                            const int* __restrict__ labels, int N,
                            float* __restrict__ out, int Q) {
    int c = blockIdx.x;
    int cnt = g_cnt[c];
    if (cnt == 0) return;
    if (threadIdx.x == 0) g_cnt[c] = 0;   // self-reset for next call

    int pos = g_pos[c];
    int t   = threadIdx.x;                // 0..63, one float4 column each

    __shared__ int sidx[CAP];
    float4 acc = make_float4(0.f, 0.f, 0.f, 0.f);

    if (cnt <= CAP) {
        for (int k = t; k < cnt; k += 64) sidx[k] = g_bucket[c * CAP + k];
        __syncthreads();

        int r = 0;
        for (; r + 8 <= cnt; r += 8) {
            float4 v0 = __ldcs(feat + (size_t)sidx[r + 0] * NV4 + t);
            float4 v1 = __ldcs(feat + (size_t)sidx[r + 1] * NV4 + t);
            float4 v2 = __ldcs(feat + (size_t)sidx[r + 2] * NV4 + t);
            float4 v3 = __ldcs(feat + (size_t)sidx[r + 3] * NV4 + t);
            float4 v4 = __ldcs(feat + (size_t)sidx[r + 4] * NV4 + t);
            float4 v5 = __ldcs(feat + (size_t)sidx[r + 5] * NV4 + t);
            float4 v6 = __ldcs(feat + (size_t)sidx[r + 6] * NV4 + t);
            float4 v7 = __ldcs(feat + (size_t)sidx[r + 7] * NV4 + t);
            acc.x += (v0.x + v1.x) + (v2.x + v3.x) + (v4.x + v5.x) + (v6.x + v7.x);
            acc.y += (v0.y + v1.y) + (v2.y + v3.y) + (v4.y + v5.y) + (v6.y + v7.y);
            acc.z += (v0.z + v1.z) + (v2.z + v3.z) + (v4.z + v5.z) + (v6.z + v7.z);
            acc.w += (v0.w + v1.w) + (v2.w + v3.w) + (v4.w + v5.w) + (v6.w + v7.w);
        }
        for (; r < cnt; r++) {
            float4 v = __ldcs(feat + (size_t)sidx[r] * NV4 + t);
            acc.x += v.x; acc.y += v.y; acc.z += v.z; acc.w += v.w;
        }
    } else {
        // Generic fallback: rescan all labels (correct for any distribution).
        for (int i = 0; i < N; i++) {
            if (__ldg(&labels[i]) == c) {
                float4 v = __ldcs(feat + (size_t)i * NV4 + t);
                acc.x += v.x; acc.y += v.y; acc.z += v.z; acc.w += v.w;
            }
        }
    }

    float inv = 1.0f / (float)cnt;
    float4 o = make_float4(acc.x * inv, acc.y * inv, acc.z * inv, acc.w * inv);
    ((float4*)out)[(size_t)pos * NV4 + t] = o;
    if (t == 0) out[(size_t)Q * FEAT + pos] = (float)c;
}

// ---------------------------------------------------------------------------
// Launch.  Inputs: features f32[N,256], pid_labels i32[N],
//   large_batch_queue f32[Q,256], queue_label f32[Q], tail i32[1]
// Output: [new_queue f32[Q,256] | new_label f32[Q]]
// ---------------------------------------------------------------------------
extern "C" void kernel_launch(void* const* d_in, const int* in_sizes, int n_in,
                              void* d_out, int out_size) {
    const float4* feat    = (const float4*)d_in[0];
    const int*    labels  = (const int*)d_in[1];
    const float4* queue0  = (const float4*)d_in[2];
    const float*  qlabel0 = (const float*)d_in[3];
    const int*    tail_p  = (const int*)d_in[4];

    int N = in_sizes[1];              // 131072
    int Q = in_sizes[3];              // 11064
    float* out = (float*)d_out;

    // 1) count + bucket (one contended-atomic pass)
    {
        int threads = 256;
        int blocks = (N + threads - 1) / threads;
        bucket_count_kernel<<<blocks, threads>>>(labels, N);
    }
    // 2) presence scan -> positions + write window
    scan_kernel<<<1, 1024>>>(tail_p, Q);
    // 3) init output, skipping the window mean_kernel will write
    {
        int total = Q * NV4 + Q;
        int threads = 256;
        int blocks = (total + threads - 1) / threads;
        init_out_kernel<<<blocks, threads>>>(queue0, qlabel0, out, Q);
    }
    // 4) gather + mean + scatter (also self-resets g_cnt)
    mean_kernel<<<NC, 64>>>(feat, labels, N, out, Q);
}